// round 15
// baseline (speedup 1.0000x reference)
#include <cuda_runtime.h>
#include <cuda_fp16.h>
#include <cstdint>
#include <math.h>

#define EMBED 1024
#define HEADS 16
#define HDIM 64
#define FFN 4096
#define BB 2
#define SS 2048
#define ROWS (BB * SS)  // 4096
#define QKVS 3072       // fused qkv row stride

// ---------------- scratch (static device globals; no allocation) ------------
__device__ __half g_nh[ROWS * EMBED];      // LN1 out
__device__ __half g_qkvh[ROWS * QKVS];     // fused QKV (rope applied in epilogue)
__device__ __half g_attnh[ROWS * EMBED];   // attention out
__device__ float  g_x1[ROWS * EMBED];      // residual after attn (fp32)
__device__ __half g_n2h[ROWS * EMBED];     // LN2 out
__device__ __half g_hh[ROWS * FFN];        // FFN1 out
__device__ float  g_bqkv[QKVS];            // concat bias
// fp16 weights, ROW-MAJOR [K][N]
__device__ __half g_wqkv[EMBED * QKVS];
__device__ __half g_wo[EMBED * EMBED];
__device__ __half g_w1[EMBED * FFN];
__device__ __half g_w2[FFN * EMBED];

__device__ __forceinline__ uint32_t smem_u32(const void* p) {
    uint32_t a;
    asm("{ .reg .u64 t; cvta.to.shared.u64 t, %1; cvt.u32.u64 %0, t; }" : "=r"(a) : "l"(p));
    return a;
}
__device__ __forceinline__ float ex2f(float x) {
    float y;
    asm("ex2.approx.f32 %0, %1;" : "=f"(y) : "f"(x));
    return y;
}

#define CP_ASYNC16(smem, gptr) \
    asm volatile("cp.async.cg.shared.global [%0], [%1], 16;" :: "r"(smem), "l"(gptr))
#define CP_COMMIT() asm volatile("cp.async.commit_group;" ::: "memory")

#define MMA16816(C, A0, A1, A2, A3, B0, B1) \
    asm volatile( \
        "mma.sync.aligned.m16n8k16.row.col.f32.f16.f16.f32 " \
        "{%0,%1,%2,%3}, {%4,%5,%6,%7}, {%8,%9}, {%0,%1,%2,%3};" \
        : "+f"((C)[0]), "+f"((C)[1]), "+f"((C)[2]), "+f"((C)[3]) \
        : "r"(A0), "r"(A1), "r"(A2), "r"(A3), "r"(B0), "r"(B1))

#define LDMX4(R0, R1, R2, R3, addr) \
    asm volatile("ldmatrix.sync.aligned.m8n8.x4.shared.b16 {%0,%1,%2,%3}, [%4];" \
                 : "=r"(R0), "=r"(R1), "=r"(R2), "=r"(R3) : "r"(addr))
#define LDMX4T(R0, R1, R2, R3, addr) \
    asm volatile("ldmatrix.sync.aligned.m8n8.x4.trans.shared.b16 {%0,%1,%2,%3}, [%4];" \
                 : "=r"(R0), "=r"(R1), "=r"(R2), "=r"(R3) : "r"(addr))

// ---------------- layernorm (fp32 in, fp16 out), vectorized ------------------
__global__ void ln_kernel(const float* __restrict__ x, const float* __restrict__ g,
                          const float* __restrict__ b, __half* __restrict__ out) {
    int row = blockIdx.x;
    const float* xr = x + (size_t)row * EMBED;
    int t = threadIdx.x;  // 256
    float4 v = *(const float4*)&xr[t * 4];
    float s = v.x + v.y + v.z + v.w;
    float s2 = v.x * v.x + v.y * v.y + v.z * v.z + v.w * v.w;
#pragma unroll
    for (int o = 16; o > 0; o >>= 1) {
        s += __shfl_xor_sync(0xFFFFFFFFu, s, o);
        s2 += __shfl_xor_sync(0xFFFFFFFFu, s2, o);
    }
    __shared__ float sh[2][8];
    int w = t >> 5, lane = t & 31;
    if (lane == 0) { sh[0][w] = s; sh[1][w] = s2; }
    __syncthreads();
    s = 0.f; s2 = 0.f;
#pragma unroll
    for (int i = 0; i < 8; i++) { s += sh[0][i]; s2 += sh[1][i]; }
    float mean = s * (1.0f / EMBED);
    float var = s2 * (1.0f / EMBED) - mean * mean;
    float r = rsqrtf(var + 1e-5f);
    float4 gv = *(const float4*)&g[t * 4];
    float4 bv = *(const float4*)&b[t * 4];
    __half2 h0 = __floats2half2_rn((v.x - mean) * r * gv.x + bv.x,
                                   (v.y - mean) * r * gv.y + bv.y);
    __half2 h1 = __floats2half2_rn((v.z - mean) * r * gv.z + bv.z,
                                   (v.w - mean) * r * gv.w + bv.w);
    uint2 o = make_uint2(*(uint32_t*)&h0, *(uint32_t*)&h1);
    *(uint2*)&out[(size_t)row * EMBED + t * 4] = o;
}

// ---------------- weight cast: QKV part (+ bias concat) ----------------------
// 786432 float4 units, 4/thread -> 768 blocks x 256
__global__ void convert_qkv(
    const float* __restrict__ Wq, const float* __restrict__ Wk,
    const float* __restrict__ Wv, __half* __restrict__ wqkv,
    const float* __restrict__ bq, const float* __restrict__ bk,
    const float* __restrict__ bv, float* __restrict__ bqkv) {
    int base = blockIdx.x * 256 + threadIdx.x;
#pragma unroll
    for (int u = 0; u < 4; u++) {
        int id = base + u * 196608;
        int k = id / 768, c4 = id - k * 768;
        int n = c4 * 4;
        int sel = n >> 10;
        const float* src = sel == 0 ? Wq : (sel == 1 ? Wk : Wv);
        float4 v = *(const float4*)&src[(size_t)k * 1024 + (n & 1023)];
        __half2 h0 = __floats2half2_rn(v.x, v.y), h1 = __floats2half2_rn(v.z, v.w);
        *(uint2*)&wqkv[(size_t)k * QKVS + n] =
            make_uint2(*(uint32_t*)&h0, *(uint32_t*)&h1);
    }
    if (blockIdx.x < 12) {
        int i = blockIdx.x * 256 + threadIdx.x;  // 0..3071
        int r = i >> 10, c = i & 1023;
        bqkv[i] = r == 0 ? bq[c] : (r == 1 ? bk[c] : bv[c]);
    }
}

// ---------------- weight cast: Wo/W1/W2 part ---------------------------------
// 2359296 float4 units (wo 262144, w1 1048576, w2 1048576), 4/thread -> 2304 blocks
__global__ void convert_rest(
    const float* __restrict__ Wo, const float* __restrict__ W1,
    const float* __restrict__ W2, __half* __restrict__ wo,
    __half* __restrict__ w1, __half* __restrict__ w2) {
    int base = blockIdx.x * 256 + threadIdx.x;
#pragma unroll
    for (int u = 0; u < 4; u++) {
        int id = base + u * 589824;
        const float* S;
        __half* D;
        if (id < 262144) { S = Wo; D = wo; }
        else if (id < 262144 + 1048576) { id -= 262144; S = W1; D = w1; }
        else { id -= 262144 + 1048576; S = W2; D = w2; }
        float4 v = *(const float4*)&S[(size_t)id * 4];
        __half2 h0 = __floats2half2_rn(v.x, v.y), h1 = __floats2half2_rn(v.z, v.w);
        *(uint2*)&D[(size_t)id * 4] = make_uint2(*(uint32_t*)&h0, *(uint32_t*)&h1);
    }
}

// ---------------- fp16 mma.sync GEMM (proven config) + optional RoPE epilogue
#define STAGES 3
#define A_STG (128 * 64)  // halves
#define B_STG (64 * 128)
#define GEMM_SMEM (STAGES * (A_STG + B_STG) * 2)  // 98304 B

template <bool GELU, bool RES, bool HOUT, bool ROPE>
__global__ __launch_bounds__(256, 2) void gemm_h(
    const __half* __restrict__ A, const __half* __restrict__ W,
    const float* __restrict__ bias, const float* __restrict__ res,
    void* __restrict__ Cout, int M, int N, int K,
    const float* __restrict__ rc, const float* __restrict__ rs) {
    extern __shared__ __half smh[];
    uint32_t sA0 = smem_u32(smh);
    uint32_t sB0 = sA0 + STAGES * A_STG * 2;

    int t = threadIdx.x;
    int wid = t >> 5, lane = t & 31;
    int warp_m = wid & 1;
    int warp_n = wid >> 1;

    int m0 = blockIdx.y * 128;
    int n0 = blockIdx.x * 128;
    const int nsteps = K / 64;

    float acc[4][4][4];
#pragma unroll
    for (int i = 0; i < 4; i++)
#pragma unroll
        for (int j = 0; j < 4; j++)
#pragma unroll
            for (int k = 0; k < 4; k++) acc[i][j][k] = 0.f;

    auto load_stage = [&](int st, int k0) {
        uint32_t sa = sA0 + st * A_STG * 2;
        uint32_t sb = sB0 + st * B_STG * 2;
#pragma unroll
        for (int p = 0; p < 4; p++) {
            int idx = t + p * 256;
            int row = idx >> 3, c = idx & 7;
            int cs = c ^ (row & 7);
            CP_ASYNC16(sa + (uint32_t)(row * 128 + cs * 16),
                       &A[(size_t)(m0 + row) * K + k0 + c * 8]);
        }
#pragma unroll
        for (int p = 0; p < 4; p++) {
            int idx = t + p * 256;
            int row = idx >> 4, c = idx & 15;
            int cs = (c & 8) | ((c ^ row) & 7);
            CP_ASYNC16(sb + (uint32_t)(row * 256 + cs * 16),
                       &W[(size_t)(k0 + row) * N + n0 + c * 8]);
        }
    };

    load_stage(0, 0);
    CP_COMMIT();
    if (nsteps > 1) { load_stage(1, 64); CP_COMMIT(); }

    int a_row_l = lane & 15;
    int a_chl = lane >> 4;
    int b_g = lane >> 3;
    int b_row_l = ((b_g & 1) << 3) + (lane & 7);
    int b_cn_l = b_g >> 1;

    for (int step = 0; step < nsteps; step++) {
        if (step + 1 < nsteps) {
            asm volatile("cp.async.wait_group 1;" ::: "memory");
        } else {
            asm volatile("cp.async.wait_group 0;" ::: "memory");
        }
        __syncthreads();
        if (step + 2 < nsteps) {
            load_stage((step + 2) % 3, (step + 2) * 64);
            CP_COMMIT();
        }

        uint32_t sa = sA0 + (step % 3) * A_STG * 2;
        uint32_t sb = sB0 + (step % 3) * B_STG * 2;

#pragma unroll
        for (int ks = 0; ks < 4; ks++) {
            uint32_t a[4][4], b[4][2];
#pragma unroll
            for (int tm = 0; tm < 4; tm++) {
                int row = warp_m * 64 + tm * 16 + a_row_l;
                int ch = ks * 2 + a_chl;
                int cs = ch ^ (row & 7);
                uint32_t addr = sa + (uint32_t)(row * 128 + cs * 16);
                LDMX4(a[tm][0], a[tm][1], a[tm][2], a[tm][3], addr);
            }
#pragma unroll
            for (int tn2 = 0; tn2 < 2; tn2++) {
                int row = ks * 16 + b_row_l;
                int cn = warp_n * 4 + tn2 * 2 + b_cn_l;
                int cs = (cn & 8) | ((cn ^ row) & 7);
                uint32_t addr = sb + (uint32_t)(row * 256 + cs * 16);
                uint32_t v0, v1, v2, v3;
                LDMX4T(v0, v1, v2, v3, addr);
                b[tn2 * 2 + 0][0] = v0; b[tn2 * 2 + 0][1] = v1;
                b[tn2 * 2 + 1][0] = v2; b[tn2 * 2 + 1][1] = v3;
            }
#pragma unroll
            for (int tm = 0; tm < 4; tm++)
#pragma unroll
                for (int tn = 0; tn < 4; tn++)
                    MMA16816(acc[tm][tn], a[tm][0], a[tm][1], a[tm][2], a[tm][3],
                             b[tn][0], b[tn][1]);
        }
    }

    int qrow = lane >> 2, qcol = lane & 3;

    if (ROPE && n0 < 2 * EMBED) {
        float* smf = (float*)smh;  // [128][132]
        __syncthreads();
#pragma unroll
        for (int tm = 0; tm < 4; tm++) {
            int r = warp_m * 64 + tm * 16 + qrow;
#pragma unroll
            for (int tn = 0; tn < 4; tn++) {
                int cl = warp_n * 32 + tn * 8 + qcol * 2;
                float2 bv = *(const float2*)&bias[n0 + cl];
                smf[r * 132 + cl] = acc[tm][tn][0] + bv.x;
                smf[r * 132 + cl + 1] = acc[tm][tn][1] + bv.y;
                smf[(r + 8) * 132 + cl] = acc[tm][tn][2] + bv.x;
                smf[(r + 8) * 132 + cl + 1] = acc[tm][tn][3] + bv.y;
            }
        }
        __syncthreads();

        const float QSC = 0.125f * 1.4426950408889634f;
        float sc = (n0 < EMBED) ? QSC : 1.0f;
        int cg = (t & 31) * 4;
        int rb = (t >> 5) * 16;
        int d = cg & 63;
        bool lowh = d < 32;
        __half* Ch = (__half*)Cout;
#pragma unroll
        for (int i = 0; i < 16; i++) {
            int r = rb + i;
            int s = (m0 + r) & (SS - 1);
            float4 cs = *(const float4*)&rc[s * HDIM + d];
            float4 sn = *(const float4*)&rs[s * HDIM + d];
            const float* rowp = smf + r * 132;
            float4 self = *(const float4*)&rowp[cg];
            float4 part = *(const float4*)&rowp[lowh ? cg + 32 : cg - 32];
            float o0, o1, o2, o3;
            if (lowh) {
                o0 = (self.x * cs.x - part.x * sn.x) * sc;
                o1 = (self.y * cs.y - part.y * sn.y) * sc;
                o2 = (self.z * cs.z - part.z * sn.z) * sc;
                o3 = (self.w * cs.w - part.w * sn.w) * sc;
            } else {
                o0 = (self.x * cs.x + part.x * sn.x) * sc;
                o1 = (self.y * cs.y + part.y * sn.y) * sc;
                o2 = (self.z * cs.z + part.z * sn.z) * sc;
                o3 = (self.w * cs.w + part.w * sn.w) * sc;
            }
            __half2 h0 = __floats2half2_rn(o0, o1), h1 = __floats2half2_rn(o2, o3);
            *(uint2*)&Ch[(size_t)(m0 + r) * N + n0 + cg] =
                make_uint2(*(uint32_t*)&h0, *(uint32_t*)&h1);
        }
        return;
    }

#pragma unroll
    for (int tm = 0; tm < 4; tm++) {
        int r0 = m0 + warp_m * 64 + tm * 16 + qrow;
#pragma unroll
        for (int tn = 0; tn < 4; tn++) {
            int c = n0 + warp_n * 32 + tn * 8 + qcol * 2;
            float2 bv = *(const float2*)&bias[c];
            float v0 = acc[tm][tn][0] + bv.x;
            float v1 = acc[tm][tn][1] + bv.y;
            float v2 = acc[tm][tn][2] + bv.x;
            float v3 = acc[tm][tn][3] + bv.y;
            if (RES) {
                float2 r1 = *(const float2*)&res[(size_t)r0 * N + c];
                float2 r2 = *(const float2*)&res[(size_t)(r0 + 8) * N + c];
                v0 += r1.x; v1 += r1.y; v2 += r2.x; v3 += r2.y;
            }
            if (GELU) {
                v0 = 0.5f * v0 * (1.0f + erff(v0 * 0.70710678118654752f));
                v1 = 0.5f * v1 * (1.0f + erff(v1 * 0.70710678118654752f));
                v2 = 0.5f * v2 * (1.0f + erff(v2 * 0.70710678118654752f));
                v3 = 0.5f * v3 * (1.0f + erff(v3 * 0.70710678118654752f));
            }
            if (HOUT) {
                __half* Ch = (__half*)Cout;
                *(__half2*)&Ch[(size_t)r0 * N + c] = __floats2half2_rn(v0, v1);
                *(__half2*)&Ch[(size_t)(r0 + 8) * N + c] = __floats2half2_rn(v2, v3);
            } else {
                float* Cf = (float*)Cout;
                *(float2*)&Cf[(size_t)r0 * N + c] = make_float2(v0, v1);
                *(float2*)&Cf[(size_t)(r0 + 8) * N + c] = make_float2(v2, v3);
            }
        }
    }
}

// ---------------- tensor-core causal flash attention (proven) ----------------
#define ATT_STRIDE 72
#define ATT_STG (64 * ATT_STRIDE)
#define ATT_STAGES 3
#define ATT_SMEM (2 * ATT_STAGES * ATT_STG * 2)  // 55296 B

__global__ __launch_bounds__(256, 2) void attn_mma(
    const __half* __restrict__ QKV, __half* __restrict__ O) {
    extern __shared__ __half smh[];
    uint32_t ks_b = smem_u32(smh);
    uint32_t vs_b = ks_b + ATT_STAGES * ATT_STG * 2;

    int tid = threadIdx.x;
    int w = tid >> 5, lane = tid & 31;
    int t4 = lane & 3, l4 = lane >> 2;
    int bh = blockIdx.y, b = bh >> 4, h = bh & 15;
    int qt = (gridDim.x - 1) - blockIdx.x;
    int q0 = qt * 128;

    const __half* Qh = QKV;
    const __half* Kh = QKV + EMBED;
    const __half* Vh = QKV + 2 * EMBED;

    uint32_t qa[4][4];
    {
        const __half* qb = Qh + (size_t)(b * SS + q0 + w * 16 + l4) * QKVS + h * 64;
#pragma unroll
        for (int kt = 0; kt < 4; kt++) {
            qa[kt][0] = *(const uint32_t*)(qb + kt * 16 + 2 * t4);
            qa[kt][1] = *(const uint32_t*)(qb + 8 * QKVS + kt * 16 + 2 * t4);
            qa[kt][2] = *(const uint32_t*)(qb + kt * 16 + 2 * t4 + 8);
            qa[kt][3] = *(const uint32_t*)(qb + 8 * QKVS + kt * 16 + 2 * t4 + 8);
        }
    }

    float o[8][4];
#pragma unroll
    for (int j = 0; j < 8; j++) { o[j][0] = o[j][1] = o[j][2] = o[j][3] = 0.f; }
    float mA = -1e30f, mB = -1e30f, lA = 0.f, lB = 0.f;

    int qA = q0 + w * 16 + l4;
    int qB = qA + 8;
    int ntiles = 2 * qt + 2;

    int b_row_l = ((lane >> 4) << 3) + (lane & 7);
    int b_col_l = ((lane >> 3) & 1) << 3;

    auto load_tile = [&](int st, int k0) {
#pragma unroll
        for (int p = 0; p < 2; p++) {
            int fi = tid + p * 256;
            int row = fi >> 3, c = fi & 7;
            uint32_t off = (uint32_t)(st * ATT_STG + row * ATT_STRIDE + c * 8) * 2;
            const __half* kg = Kh + (size_t)(b * SS + k0 + row) * QKVS + h * 64 + c * 8;
            const __half* vg = Vh + (size_t)(b * SS + k0 + row) * QKVS + h * 64 + c * 8;
            CP_ASYNC16(ks_b + off, kg);
            CP_ASYNC16(vs_b + off, vg);
        }
    };

    load_tile(0, 0);
    CP_COMMIT();
    if (ntiles > 1) { load_tile(1, 64); CP_COMMIT(); }

    for (int kt = 0; kt < ntiles; kt++) {
        if (kt + 1 < ntiles) {
            asm volatile("cp.async.wait_group 1;" ::: "memory");
        } else {
            asm volatile("cp.async.wait_group 0;" ::: "memory");
        }
        __syncthreads();
        if (kt + 2 < ntiles) {
            load_tile((kt + 2) % ATT_STAGES, (kt + 2) * 64);
            CP_COMMIT();
        }

        uint32_t kst = ks_b + (uint32_t)((kt % ATT_STAGES) * ATT_STG) * 2;
        uint32_t vst = vs_b + (uint32_t)((kt % ATT_STAGES) * ATT_STG) * 2;

        float s[8][4];
#pragma unroll
        for (int j = 0; j < 8; j++) { s[j][0] = s[j][1] = s[j][2] = s[j][3] = 0.f; }
#pragma unroll
        for (int k4 = 0; k4 < 4; k4++) {
#pragma unroll
            for (int jj = 0; jj < 4; jj++) {
                int row = jj * 16 + b_row_l;
                uint32_t addr = kst + (uint32_t)(row * ATT_STRIDE + k4 * 16 + b_col_l) * 2;
                uint32_t r0, r1, r2, r3;
                LDMX4(r0, r1, r2, r3, addr);
                MMA16816(s[2 * jj], qa[k4][0], qa[k4][1], qa[k4][2], qa[k4][3], r0, r1);
                MMA16816(s[2 * jj + 1], qa[k4][0], qa[k4][1], qa[k4][2], qa[k4][3], r2, r3);
            }
        }

        int k0 = kt * 64;
        if (kt >= 2 * qt) {
#pragma unroll
            for (int j = 0; j < 8; j++) {
                int key = k0 + j * 8 + 2 * t4;
                if (key > qA) s[j][0] = -1e30f;
                if (key + 1 > qA) s[j][1] = -1e30f;
                if (key > qB) s[j][2] = -1e30f;
                if (key + 1 > qB) s[j][3] = -1e30f;
            }
        }

        float mtA = -1e30f, mtB = -1e30f;
#pragma unroll
        for (int j = 0; j < 8; j++) {
            mtA = fmaxf(mtA, fmaxf(s[j][0], s[j][1]));
            mtB = fmaxf(mtB, fmaxf(s[j][2], s[j][3]));
        }
        mtA = fmaxf(mtA, __shfl_xor_sync(0xFFFFFFFFu, mtA, 1));
        mtA = fmaxf(mtA, __shfl_xor_sync(0xFFFFFFFFu, mtA, 2));
        mtB = fmaxf(mtB, __shfl_xor_sync(0xFFFFFFFFu, mtB, 1));
        mtB = fmaxf(mtB, __shfl_xor_sync(0xFFFFFFFFu, mtB, 2));
        float mAn = fmaxf(mA, mtA), mBn = fmaxf(mB, mtB);
        float corrA = ex2f(mA - mAn), corrB = ex2f(mB - mBn);

        float sumA = 0.f, sumB = 0.f;
#pragma unroll
        for (int j = 0; j < 8; j++) {
            s[j][0] = ex2f(s[j][0] - mAn);
            s[j][1] = ex2f(s[j][1] - mAn);
            s[j][2] = ex2f(s[j][2] - mBn);
            s[j][3] = ex2f(s[j][3] - mBn);
            sumA += s[j][0] + s[j][1];
            sumB += s[j][2] + s[j][3];
        }
        lA = lA * corrA + sumA;
        lB = lB * corrB + sumB;
        mA = mAn; mB = mBn;
#pragma unroll
        for (int j = 0; j < 8; j++) {
            o[j][0] *= corrA; o[j][1] *= corrA;
            o[j][2] *= corrB; o[j][3] *= corrB;
        }

#pragma unroll
        for (int k4 = 0; k4 < 4; k4++) {
            __half2 h0 = __floats2half2_rn(s[2 * k4][0], s[2 * k4][1]);
            __half2 h1 = __floats2half2_rn(s[2 * k4][2], s[2 * k4][3]);
            __half2 h2 = __floats2half2_rn(s[2 * k4 + 1][0], s[2 * k4 + 1][1]);
            __half2 h3 = __floats2half2_rn(s[2 * k4 + 1][2], s[2 * k4 + 1][3]);
            uint32_t pa0 = *(uint32_t*)&h0, pa1 = *(uint32_t*)&h1;
            uint32_t pa2 = *(uint32_t*)&h2, pa3 = *(uint32_t*)&h3;
#pragma unroll
            for (int jj = 0; jj < 4; jj++) {
                int g = lane >> 3, r = lane & 7;
                uint32_t addr = vst +
                    (uint32_t)((k4 * 16 + (g & 1) * 8 + r) * ATT_STRIDE +
                               (2 * jj + (g >> 1)) * 8) * 2;
                uint32_t v0, v1, v2, v3;
                LDMX4T(v0, v1, v2, v3, addr);
                MMA16816(o[2 * jj], pa0, pa1, pa2, pa3, v0, v1);
                MMA16816(o[2 * jj + 1], pa0, pa1, pa2, pa3, v2, v3);
            }
        }
    }

    lA += __shfl_xor_sync(0xFFFFFFFFu, lA, 1);
    lA += __shfl_xor_sync(0xFFFFFFFFu, lA, 2);
    lB += __shfl_xor_sync(0xFFFFFFFFu, lB, 1);
    lB += __shfl_xor_sync(0xFFFFFFFFu, lB, 2);
    float invA = 1.0f / lA, invB = 1.0f / lB;
    __half* oA = O + (size_t)(b * SS + qA) * EMBED + h * 64;
    __half* oB = O + (size_t)(b * SS + qB) * EMBED + h * 64;
#pragma unroll
    for (int j = 0; j < 8; j++) {
        int c = j * 8 + 2 * t4;
        *(__half2*)(oA + c) = __floats2half2_rn(o[j][0] * invA, o[j][1] * invA);
        *(__half2*)(oB + c) = __floats2half2_rn(o[j][2] * invB, o[j][3] * invB);
    }
}

// ---------------- launch ------------------------------------------------------
extern "C" void kernel_launch(void* const* d_in, const int* in_sizes, int n_in,
                              void* d_out, int out_size) {
    const float* x   = (const float*)d_in[0];
    const float* rc  = (const float*)d_in[1];
    const float* rs  = (const float*)d_in[2];
    const float* Wq  = (const float*)d_in[3];
    const float* bq  = (const float*)d_in[4];
    const float* Wk  = (const float*)d_in[5];
    const float* bk  = (const float*)d_in[6];
    const float* Wv  = (const float*)d_in[7];
    const float* bv  = (const float*)d_in[8];
    const float* Wo  = (const float*)d_in[9];
    const float* bo  = (const float*)d_in[10];
    const float* W1  = (const float*)d_in[11];
    const float* b1  = (const float*)d_in[12];
    const float* W2  = (const float*)d_in[13];
    const float* b2  = (const float*)d_in[14];
    const float* g1  = (const float*)d_in[15];
    const float* be1 = (const float*)d_in[16];
    const float* g2  = (const float*)d_in[17];
    const float* be2 = (const float*)d_in[18];
    float* out = (float*)d_out;

    __half *nh, *qkvh, *attnh, *n2h, *hh;
    __half *wqkv, *wo, *w1, *w2;
    float *x1_, *bqkv;
    cudaGetSymbolAddress((void**)&nh, g_nh);
    cudaGetSymbolAddress((void**)&qkvh, g_qkvh);
    cudaGetSymbolAddress((void**)&attnh, g_attnh);
    cudaGetSymbolAddress((void**)&x1_, g_x1);
    cudaGetSymbolAddress((void**)&n2h, g_n2h);
    cudaGetSymbolAddress((void**)&hh, g_hh);
    cudaGetSymbolAddress((void**)&wqkv, g_wqkv);
    cudaGetSymbolAddress((void**)&wo, g_wo);
    cudaGetSymbolAddress((void**)&w1, g_w1);
    cudaGetSymbolAddress((void**)&w2, g_w2);
    cudaGetSymbolAddress((void**)&bqkv, g_bqkv);

    static bool init_done = false;
    static cudaStream_t sLn, sRest;
    static cudaEvent_t eRoot, eLn, eRest;
    if (!init_done) {
        cudaFuncSetAttribute(gemm_h<false, false, true, true>,
                             cudaFuncAttributeMaxDynamicSharedMemorySize, GEMM_SMEM);
        cudaFuncSetAttribute(gemm_h<false, true, false, false>,
                             cudaFuncAttributeMaxDynamicSharedMemorySize, GEMM_SMEM);
        cudaFuncSetAttribute(gemm_h<true, false, true, false>,
                             cudaFuncAttributeMaxDynamicSharedMemorySize, GEMM_SMEM);
        cudaFuncSetAttribute(attn_mma,
                             cudaFuncAttributeMaxDynamicSharedMemorySize, ATT_SMEM);
        cudaStreamCreateWithFlags(&sLn, cudaStreamNonBlocking);
        cudaStreamCreateWithFlags(&sRest, cudaStreamNonBlocking);
        cudaEventCreateWithFlags(&eRoot, cudaEventDisableTiming);
        cudaEventCreateWithFlags(&eLn, cudaEventDisableTiming);
        cudaEventCreateWithFlags(&eRest, cudaEventDisableTiming);
        init_done = true;
    }

    // fork: ln1 on sLn, convert_rest on sRest, convert_qkv on main stream
    cudaEventRecord(eRoot, 0);
    cudaStreamWaitEvent(sLn, eRoot, 0);
    cudaStreamWaitEvent(sRest, eRoot, 0);

    ln_kernel<<<ROWS, 256, 0, sLn>>>(x, g1, be1, nh);
    cudaEventRecord(eLn, sLn);

    convert_rest<<<2304, 256, 0, sRest>>>(Wo, W1, W2, wo, w1, w2);
    cudaEventRecord(eRest, sRest);

    convert_qkv<<<768, 256>>>(Wq, Wk, Wv, wqkv, bq, bk, bv, bqkv);

    // join ln1 before QKV GEMM
    cudaStreamWaitEvent(0, eLn, 0);

    dim3 gQKV(QKVS / 128, ROWS / 128);  // (24, 32)
    dim3 gE(EMBED / 128, ROWS / 128);   // (8, 32)
    dim3 gF(FFN / 128, ROWS / 128);     // (32, 32)

    gemm_h<false, false, true, true><<<gQKV, 256, GEMM_SMEM>>>(
        nh, wqkv, bqkv, nullptr, qkvh, ROWS, QKVS, EMBED, rc, rs);

    attn_mma<<<dim3(SS / 128, BB * HEADS), 256, ATT_SMEM>>>(qkvh, attnh);

    // join convert_rest before Wo GEMM
    cudaStreamWaitEvent(0, eRest, 0);

    gemm_h<false, true, false, false><<<gE, 256, GEMM_SMEM>>>(
        attnh, wo, bo, x, x1_, ROWS, EMBED, EMBED, nullptr, nullptr);

    ln_kernel<<<ROWS, 256>>>(x1_, g2, be2, n2h);

    gemm_h<true, false, true, false><<<gF, 256, GEMM_SMEM>>>(
        n2h, w1, b1, nullptr, hh, ROWS, FFN, EMBED, nullptr, nullptr);
    gemm_h<false, true, false, false><<<gE, 256, GEMM_SMEM>>>(
        hh, w2, b2, x1_, out, ROWS, EMBED, FFN, nullptr, nullptr);
}

// round 16
// speedup vs baseline: 1.0054x; 1.0054x over previous
#include <cuda_runtime.h>
#include <cuda_fp16.h>
#include <cstdint>
#include <math.h>

#define EMBED 1024
#define HEADS 16
#define HDIM 64
#define FFN 4096
#define BB 2
#define SS 2048
#define ROWS (BB * SS)  // 4096
#define QKVS 3072       // fused qkv row stride

// ---------------- scratch (static device globals; no allocation) ------------
__device__ __half g_nh[ROWS * EMBED];      // LN1 out
__device__ __half g_qkvh[ROWS * QKVS];     // fused QKV (rope applied in epilogue)
__device__ __half g_attnh[ROWS * EMBED];   // attention out
__device__ float  g_x1[ROWS * EMBED];      // residual after attn (fp32)
__device__ __half g_n2h[ROWS * EMBED];     // LN2 out
__device__ __half g_hh[ROWS * FFN];        // FFN1 out
__device__ float  g_bqkv[QKVS];            // concat bias
// fp16 weights, ROW-MAJOR [K][N]
__device__ __half g_wqkv[EMBED * QKVS];
__device__ __half g_wo[EMBED * EMBED];
__device__ __half g_w1[EMBED * FFN];
__device__ __half g_w2[FFN * EMBED];

__device__ __forceinline__ uint32_t smem_u32(const void* p) {
    uint32_t a;
    asm("{ .reg .u64 t; cvta.to.shared.u64 t, %1; cvt.u32.u64 %0, t; }" : "=r"(a) : "l"(p));
    return a;
}
__device__ __forceinline__ float ex2f(float x) {
    float y;
    asm("ex2.approx.f32 %0, %1;" : "=f"(y) : "f"(x));
    return y;
}
__device__ __forceinline__ uint32_t ex2h2(uint32_t x) {
    uint32_t y;
    asm("ex2.approx.f16x2 %0, %1;" : "=r"(y) : "r"(x));
    return y;
}

#define CP_ASYNC16(smem, gptr) \
    asm volatile("cp.async.cg.shared.global [%0], [%1], 16;" :: "r"(smem), "l"(gptr))
#define CP_COMMIT() asm volatile("cp.async.commit_group;" ::: "memory")

#define MMA16816(C, A0, A1, A2, A3, B0, B1) \
    asm volatile( \
        "mma.sync.aligned.m16n8k16.row.col.f32.f16.f16.f32 " \
        "{%0,%1,%2,%3}, {%4,%5,%6,%7}, {%8,%9}, {%0,%1,%2,%3};" \
        : "+f"((C)[0]), "+f"((C)[1]), "+f"((C)[2]), "+f"((C)[3]) \
        : "r"(A0), "r"(A1), "r"(A2), "r"(A3), "r"(B0), "r"(B1))

#define LDMX4(R0, R1, R2, R3, addr) \
    asm volatile("ldmatrix.sync.aligned.m8n8.x4.shared.b16 {%0,%1,%2,%3}, [%4];" \
                 : "=r"(R0), "=r"(R1), "=r"(R2), "=r"(R3) : "r"(addr))
#define LDMX4T(R0, R1, R2, R3, addr) \
    asm volatile("ldmatrix.sync.aligned.m8n8.x4.trans.shared.b16 {%0,%1,%2,%3}, [%4];" \
                 : "=r"(R0), "=r"(R1), "=r"(R2), "=r"(R3) : "r"(addr))

// ---------------- layernorm (fp32 in, fp16 out), vectorized ------------------
__global__ void ln_kernel(const float* __restrict__ x, const float* __restrict__ g,
                          const float* __restrict__ b, __half* __restrict__ out) {
    int row = blockIdx.x;
    const float* xr = x + (size_t)row * EMBED;
    int t = threadIdx.x;  // 256
    float4 v = *(const float4*)&xr[t * 4];
    float s = v.x + v.y + v.z + v.w;
    float s2 = v.x * v.x + v.y * v.y + v.z * v.z + v.w * v.w;
#pragma unroll
    for (int o = 16; o > 0; o >>= 1) {
        s += __shfl_xor_sync(0xFFFFFFFFu, s, o);
        s2 += __shfl_xor_sync(0xFFFFFFFFu, s2, o);
    }
    __shared__ float sh[2][8];
    int w = t >> 5, lane = t & 31;
    if (lane == 0) { sh[0][w] = s; sh[1][w] = s2; }
    __syncthreads();
    s = 0.f; s2 = 0.f;
#pragma unroll
    for (int i = 0; i < 8; i++) { s += sh[0][i]; s2 += sh[1][i]; }
    float mean = s * (1.0f / EMBED);
    float var = s2 * (1.0f / EMBED) - mean * mean;
    float r = rsqrtf(var + 1e-5f);
    float4 gv = *(const float4*)&g[t * 4];
    float4 bv = *(const float4*)&b[t * 4];
    __half2 h0 = __floats2half2_rn((v.x - mean) * r * gv.x + bv.x,
                                   (v.y - mean) * r * gv.y + bv.y);
    __half2 h1 = __floats2half2_rn((v.z - mean) * r * gv.z + bv.z,
                                   (v.w - mean) * r * gv.w + bv.w);
    uint2 o = make_uint2(*(uint32_t*)&h0, *(uint32_t*)&h1);
    *(uint2*)&out[(size_t)row * EMBED + t * 4] = o;
}

// ---------------- weight cast fp32 -> fp16, MLP=4, + bias concat -------------
__device__ __forceinline__ void cvt_unit(
    int id,
    const float* __restrict__ Wq, const float* __restrict__ Wk,
    const float* __restrict__ Wv, const float* __restrict__ Wo,
    const float* __restrict__ W1, const float* __restrict__ W2,
    __half* __restrict__ wqkv, __half* __restrict__ wo,
    __half* __restrict__ w1, __half* __restrict__ w2) {
    if (id < 786432) {
        int k = id / 768, c4 = id - k * 768;
        int n = c4 * 4;
        int sel = n >> 10;
        const float* src = sel == 0 ? Wq : (sel == 1 ? Wk : Wv);
        float4 v = *(const float4*)&src[(size_t)k * 1024 + (n & 1023)];
        __half2 h0 = __floats2half2_rn(v.x, v.y), h1 = __floats2half2_rn(v.z, v.w);
        *(uint2*)&wqkv[(size_t)k * QKVS + n] =
            make_uint2(*(uint32_t*)&h0, *(uint32_t*)&h1);
        return;
    }
    id -= 786432;
    const float* S;
    __half* D;
    if (id < 262144) { S = Wo; D = wo; }
    else if (id < 262144 + 1048576) { id -= 262144; S = W1; D = w1; }
    else { id -= 262144 + 1048576; S = W2; D = w2; }
    float4 v = *(const float4*)&S[(size_t)id * 4];
    __half2 h0 = __floats2half2_rn(v.x, v.y), h1 = __floats2half2_rn(v.z, v.w);
    *(uint2*)&D[(size_t)id * 4] = make_uint2(*(uint32_t*)&h0, *(uint32_t*)&h1);
}

__global__ void convert_weights(
    const float* __restrict__ Wq, const float* __restrict__ Wk,
    const float* __restrict__ Wv, const float* __restrict__ Wo,
    const float* __restrict__ W1, const float* __restrict__ W2,
    __half* __restrict__ wqkv, __half* __restrict__ wo,
    __half* __restrict__ w1, __half* __restrict__ w2,
    const float* __restrict__ bq, const float* __restrict__ bk,
    const float* __restrict__ bv, float* __restrict__ bqkv) {
    int base = blockIdx.x * 256 + threadIdx.x;
#pragma unroll
    for (int u = 0; u < 4; u++)
        cvt_unit(base + u * 786432, Wq, Wk, Wv, Wo, W1, W2, wqkv, wo, w1, w2);
    if (blockIdx.x < 12) {
        int i = blockIdx.x * 256 + threadIdx.x;  // 0..3071
        int r = i >> 10, c = i & 1023;
        bqkv[i] = r == 0 ? bq[c] : (r == 1 ? bk[c] : bv[c]);
    }
}

// ---------------- fp16 mma.sync GEMM (proven config) + optional RoPE epilogue
#define STAGES 3
#define A_STG (128 * 64)  // halves
#define B_STG (64 * 128)
#define GEMM_SMEM (STAGES * (A_STG + B_STG) * 2)  // 98304 B

template <bool GELU, bool RES, bool HOUT, bool ROPE>
__global__ __launch_bounds__(256, 2) void gemm_h(
    const __half* __restrict__ A, const __half* __restrict__ W,
    const float* __restrict__ bias, const float* __restrict__ res,
    void* __restrict__ Cout, int M, int N, int K,
    const float* __restrict__ rc, const float* __restrict__ rs) {
    extern __shared__ __half smh[];
    uint32_t sA0 = smem_u32(smh);
    uint32_t sB0 = sA0 + STAGES * A_STG * 2;

    int t = threadIdx.x;
    int wid = t >> 5, lane = t & 31;
    int warp_m = wid & 1;
    int warp_n = wid >> 1;

    int m0 = blockIdx.y * 128;
    int n0 = blockIdx.x * 128;
    const int nsteps = K / 64;

    float acc[4][4][4];
#pragma unroll
    for (int i = 0; i < 4; i++)
#pragma unroll
        for (int j = 0; j < 4; j++)
#pragma unroll
            for (int k = 0; k < 4; k++) acc[i][j][k] = 0.f;

    auto load_stage = [&](int st, int k0) {
        uint32_t sa = sA0 + st * A_STG * 2;
        uint32_t sb = sB0 + st * B_STG * 2;
#pragma unroll
        for (int p = 0; p < 4; p++) {
            int idx = t + p * 256;
            int row = idx >> 3, c = idx & 7;
            int cs = c ^ (row & 7);
            CP_ASYNC16(sa + (uint32_t)(row * 128 + cs * 16),
                       &A[(size_t)(m0 + row) * K + k0 + c * 8]);
        }
#pragma unroll
        for (int p = 0; p < 4; p++) {
            int idx = t + p * 256;
            int row = idx >> 4, c = idx & 15;
            int cs = (c & 8) | ((c ^ row) & 7);
            CP_ASYNC16(sb + (uint32_t)(row * 256 + cs * 16),
                       &W[(size_t)(k0 + row) * N + n0 + c * 8]);
        }
    };

    load_stage(0, 0);
    CP_COMMIT();
    if (nsteps > 1) { load_stage(1, 64); CP_COMMIT(); }

    int a_row_l = lane & 15;
    int a_chl = lane >> 4;
    int b_g = lane >> 3;
    int b_row_l = ((b_g & 1) << 3) + (lane & 7);
    int b_cn_l = b_g >> 1;

    for (int step = 0; step < nsteps; step++) {
        if (step + 1 < nsteps) {
            asm volatile("cp.async.wait_group 1;" ::: "memory");
        } else {
            asm volatile("cp.async.wait_group 0;" ::: "memory");
        }
        __syncthreads();
        if (step + 2 < nsteps) {
            load_stage((step + 2) % 3, (step + 2) * 64);
            CP_COMMIT();
        }

        uint32_t sa = sA0 + (step % 3) * A_STG * 2;
        uint32_t sb = sB0 + (step % 3) * B_STG * 2;

#pragma unroll
        for (int ks = 0; ks < 4; ks++) {
            uint32_t a[4][4], b[4][2];
#pragma unroll
            for (int tm = 0; tm < 4; tm++) {
                int row = warp_m * 64 + tm * 16 + a_row_l;
                int ch = ks * 2 + a_chl;
                int cs = ch ^ (row & 7);
                uint32_t addr = sa + (uint32_t)(row * 128 + cs * 16);
                LDMX4(a[tm][0], a[tm][1], a[tm][2], a[tm][3], addr);
            }
#pragma unroll
            for (int tn2 = 0; tn2 < 2; tn2++) {
                int row = ks * 16 + b_row_l;
                int cn = warp_n * 4 + tn2 * 2 + b_cn_l;
                int cs = (cn & 8) | ((cn ^ row) & 7);
                uint32_t addr = sb + (uint32_t)(row * 256 + cs * 16);
                uint32_t v0, v1, v2, v3;
                LDMX4T(v0, v1, v2, v3, addr);
                b[tn2 * 2 + 0][0] = v0; b[tn2 * 2 + 0][1] = v1;
                b[tn2 * 2 + 1][0] = v2; b[tn2 * 2 + 1][1] = v3;
            }
#pragma unroll
            for (int tm = 0; tm < 4; tm++)
#pragma unroll
                for (int tn = 0; tn < 4; tn++)
                    MMA16816(acc[tm][tn], a[tm][0], a[tm][1], a[tm][2], a[tm][3],
                             b[tn][0], b[tn][1]);
        }
    }

    int qrow = lane >> 2, qcol = lane & 3;

    if (ROPE && n0 < 2 * EMBED) {
        float* smf = (float*)smh;  // [128][132]
        __syncthreads();
#pragma unroll
        for (int tm = 0; tm < 4; tm++) {
            int r = warp_m * 64 + tm * 16 + qrow;
#pragma unroll
            for (int tn = 0; tn < 4; tn++) {
                int cl = warp_n * 32 + tn * 8 + qcol * 2;
                float2 bv = *(const float2*)&bias[n0 + cl];
                smf[r * 132 + cl] = acc[tm][tn][0] + bv.x;
                smf[r * 132 + cl + 1] = acc[tm][tn][1] + bv.y;
                smf[(r + 8) * 132 + cl] = acc[tm][tn][2] + bv.x;
                smf[(r + 8) * 132 + cl + 1] = acc[tm][tn][3] + bv.y;
            }
        }
        __syncthreads();

        const float QSC = 0.125f * 1.4426950408889634f;
        float sc = (n0 < EMBED) ? QSC : 1.0f;
        int cg = (t & 31) * 4;
        int rb = (t >> 5) * 16;
        int d = cg & 63;
        bool lowh = d < 32;
        __half* Ch = (__half*)Cout;
#pragma unroll
        for (int i = 0; i < 16; i++) {
            int r = rb + i;
            int s = (m0 + r) & (SS - 1);
            float4 cs = *(const float4*)&rc[s * HDIM + d];
            float4 sn = *(const float4*)&rs[s * HDIM + d];
            const float* rowp = smf + r * 132;
            float4 self = *(const float4*)&rowp[cg];
            float4 part = *(const float4*)&rowp[lowh ? cg + 32 : cg - 32];
            float o0, o1, o2, o3;
            if (lowh) {
                o0 = (self.x * cs.x - part.x * sn.x) * sc;
                o1 = (self.y * cs.y - part.y * sn.y) * sc;
                o2 = (self.z * cs.z - part.z * sn.z) * sc;
                o3 = (self.w * cs.w - part.w * sn.w) * sc;
            } else {
                o0 = (self.x * cs.x + part.x * sn.x) * sc;
                o1 = (self.y * cs.y + part.y * sn.y) * sc;
                o2 = (self.z * cs.z + part.z * sn.z) * sc;
                o3 = (self.w * cs.w + part.w * sn.w) * sc;
            }
            __half2 h0 = __floats2half2_rn(o0, o1), h1 = __floats2half2_rn(o2, o3);
            *(uint2*)&Ch[(size_t)(m0 + r) * N + n0 + cg] =
                make_uint2(*(uint32_t*)&h0, *(uint32_t*)&h1);
        }
        return;
    }

#pragma unroll
    for (int tm = 0; tm < 4; tm++) {
        int r0 = m0 + warp_m * 64 + tm * 16 + qrow;
#pragma unroll
        for (int tn = 0; tn < 4; tn++) {
            int c = n0 + warp_n * 32 + tn * 8 + qcol * 2;
            float2 bv = *(const float2*)&bias[c];
            float v0 = acc[tm][tn][0] + bv.x;
            float v1 = acc[tm][tn][1] + bv.y;
            float v2 = acc[tm][tn][2] + bv.x;
            float v3 = acc[tm][tn][3] + bv.y;
            if (RES) {
                float2 r1 = *(const float2*)&res[(size_t)r0 * N + c];
                float2 r2 = *(const float2*)&res[(size_t)(r0 + 8) * N + c];
                v0 += r1.x; v1 += r1.y; v2 += r2.x; v3 += r2.y;
            }
            if (GELU) {
                v0 = 0.5f * v0 * (1.0f + erff(v0 * 0.70710678118654752f));
                v1 = 0.5f * v1 * (1.0f + erff(v1 * 0.70710678118654752f));
                v2 = 0.5f * v2 * (1.0f + erff(v2 * 0.70710678118654752f));
                v3 = 0.5f * v3 * (1.0f + erff(v3 * 0.70710678118654752f));
            }
            if (HOUT) {
                __half* Ch = (__half*)Cout;
                *(__half2*)&Ch[(size_t)r0 * N + c] = __floats2half2_rn(v0, v1);
                *(__half2*)&Ch[(size_t)(r0 + 8) * N + c] = __floats2half2_rn(v2, v3);
            } else {
                float* Cf = (float*)Cout;
                *(float2*)&Cf[(size_t)r0 * N + c] = make_float2(v0, v1);
                *(float2*)&Cf[(size_t)(r0 + 8) * N + c] = make_float2(v2, v3);
            }
        }
    }
}

// ---------------- tensor-core causal flash attention --------------------------
// fp16x2 exp2: p computed directly in half2 (MUFU count 1/4, packs deleted).
#define ATT_STRIDE 72
#define ATT_STG (64 * ATT_STRIDE)
#define ATT_STAGES 3
#define ATT_SMEM (2 * ATT_STAGES * ATT_STG * 2)  // 55296 B

__global__ __launch_bounds__(256, 2) void attn_mma(
    const __half* __restrict__ QKV, __half* __restrict__ O) {
    extern __shared__ __half smh[];
    uint32_t ks_b = smem_u32(smh);
    uint32_t vs_b = ks_b + ATT_STAGES * ATT_STG * 2;

    int tid = threadIdx.x;
    int w = tid >> 5, lane = tid & 31;
    int t4 = lane & 3, l4 = lane >> 2;
    int bh = blockIdx.y, b = bh >> 4, h = bh & 15;
    int qt = (gridDim.x - 1) - blockIdx.x;
    int q0 = qt * 128;

    const __half* Qh = QKV;
    const __half* Kh = QKV + EMBED;
    const __half* Vh = QKV + 2 * EMBED;

    uint32_t qa[4][4];
    {
        const __half* qb = Qh + (size_t)(b * SS + q0 + w * 16 + l4) * QKVS + h * 64;
#pragma unroll
        for (int kt = 0; kt < 4; kt++) {
            qa[kt][0] = *(const uint32_t*)(qb + kt * 16 + 2 * t4);
            qa[kt][1] = *(const uint32_t*)(qb + 8 * QKVS + kt * 16 + 2 * t4);
            qa[kt][2] = *(const uint32_t*)(qb + kt * 16 + 2 * t4 + 8);
            qa[kt][3] = *(const uint32_t*)(qb + 8 * QKVS + kt * 16 + 2 * t4 + 8);
        }
    }

    float o[8][4];
#pragma unroll
    for (int j = 0; j < 8; j++) { o[j][0] = o[j][1] = o[j][2] = o[j][3] = 0.f; }
    float mA = -1e30f, mB = -1e30f, lA = 0.f, lB = 0.f;

    int qA = q0 + w * 16 + l4;
    int qB = qA + 8;
    int ntiles = 2 * qt + 2;

    int b_row_l = ((lane >> 4) << 3) + (lane & 7);
    int b_col_l = ((lane >> 3) & 1) << 3;

    auto load_tile = [&](int st, int k0) {
#pragma unroll
        for (int p = 0; p < 2; p++) {
            int fi = tid + p * 256;
            int row = fi >> 3, c = fi & 7;
            uint32_t off = (uint32_t)(st * ATT_STG + row * ATT_STRIDE + c * 8) * 2;
            const __half* kg = Kh + (size_t)(b * SS + k0 + row) * QKVS + h * 64 + c * 8;
            const __half* vg = Vh + (size_t)(b * SS + k0 + row) * QKVS + h * 64 + c * 8;
            CP_ASYNC16(ks_b + off, kg);
            CP_ASYNC16(vs_b + off, vg);
        }
    };

    load_tile(0, 0);
    CP_COMMIT();
    if (ntiles > 1) { load_tile(1, 64); CP_COMMIT(); }

    for (int kt = 0; kt < ntiles; kt++) {
        if (kt + 1 < ntiles) {
            asm volatile("cp.async.wait_group 1;" ::: "memory");
        } else {
            asm volatile("cp.async.wait_group 0;" ::: "memory");
        }
        __syncthreads();
        if (kt + 2 < ntiles) {
            load_tile((kt + 2) % ATT_STAGES, (kt + 2) * 64);
            CP_COMMIT();
        }

        uint32_t kst = ks_b + (uint32_t)((kt % ATT_STAGES) * ATT_STG) * 2;
        uint32_t vst = vs_b + (uint32_t)((kt % ATT_STAGES) * ATT_STG) * 2;

        float s[8][4];
#pragma unroll
        for (int j = 0; j < 8; j++) { s[j][0] = s[j][1] = s[j][2] = s[j][3] = 0.f; }
#pragma unroll
        for (int k4 = 0; k4 < 4; k4++) {
#pragma unroll
            for (int jj = 0; jj < 4; jj++) {
                int row = jj * 16 + b_row_l;
                uint32_t addr = kst + (uint32_t)(row * ATT_STRIDE + k4 * 16 + b_col_l) * 2;
                uint32_t r0, r1, r2, r3;
                LDMX4(r0, r1, r2, r3, addr);
                MMA16816(s[2 * jj], qa[k4][0], qa[k4][1], qa[k4][2], qa[k4][3], r0, r1);
                MMA16816(s[2 * jj + 1], qa[k4][0], qa[k4][1], qa[k4][2], qa[k4][3], r2, r3);
            }
        }

        int k0 = kt * 64;
        if (kt >= 2 * qt) {
#pragma unroll
            for (int j = 0; j < 8; j++) {
                int key = k0 + j * 8 + 2 * t4;
                if (key > qA) s[j][0] = -1e30f;
                if (key + 1 > qA) s[j][1] = -1e30f;
                if (key > qB) s[j][2] = -1e30f;
                if (key + 1 > qB) s[j][3] = -1e30f;
            }
        }

        float mtA = -1e30f, mtB = -1e30f;
#pragma unroll
        for (int j = 0; j < 8; j++) {
            mtA = fmaxf(mtA, fmaxf(s[j][0], s[j][1]));
            mtB = fmaxf(mtB, fmaxf(s[j][2], s[j][3]));
        }
        mtA = fmaxf(mtA, __shfl_xor_sync(0xFFFFFFFFu, mtA, 1));
        mtA = fmaxf(mtA, __shfl_xor_sync(0xFFFFFFFFu, mtA, 2));
        mtB = fmaxf(mtB, __shfl_xor_sync(0xFFFFFFFFu, mtB, 1));
        mtB = fmaxf(mtB, __shfl_xor_sync(0xFFFFFFFFu, mtB, 2));
        float mAn = fmaxf(mA, mtA), mBn = fmaxf(mB, mtB);
        float corrA = ex2f(mA - mAn), corrB = ex2f(mB - mBn);

        // p = exp2(s - m) computed directly in fp16x2; pa[j] is the PV A-frag.
        uint32_t ph[8][2];
        float sumA = 0.f, sumB = 0.f;
#pragma unroll
        for (int j = 0; j < 8; j++) {
            __half2 dA = __floats2half2_rn(s[j][0] - mAn, s[j][1] - mAn);
            __half2 dB = __floats2half2_rn(s[j][2] - mBn, s[j][3] - mBn);
            ph[j][0] = ex2h2(*(uint32_t*)&dA);
            ph[j][1] = ex2h2(*(uint32_t*)&dB);
            float2 fA = __half22float2(*(__half2*)&ph[j][0]);
            float2 fB = __half22float2(*(__half2*)&ph[j][1]);
            sumA += fA.x + fA.y;
            sumB += fB.x + fB.y;
        }
        lA = lA * corrA + sumA;
        lB = lB * corrB + sumB;
        mA = mAn; mB = mBn;
#pragma unroll
        for (int j = 0; j < 8; j++) {
            o[j][0] *= corrA; o[j][1] *= corrA;
            o[j][2] *= corrB; o[j][3] *= corrB;
        }

#pragma unroll
        for (int k4 = 0; k4 < 4; k4++) {
            uint32_t pa0 = ph[2 * k4][0], pa1 = ph[2 * k4][1];
            uint32_t pa2 = ph[2 * k4 + 1][0], pa3 = ph[2 * k4 + 1][1];
#pragma unroll
            for (int jj = 0; jj < 4; jj++) {
                int g = lane >> 3, r = lane & 7;
                uint32_t addr = vst +
                    (uint32_t)((k4 * 16 + (g & 1) * 8 + r) * ATT_STRIDE +
                               (2 * jj + (g >> 1)) * 8) * 2;
                uint32_t v0, v1, v2, v3;
                LDMX4T(v0, v1, v2, v3, addr);
                MMA16816(o[2 * jj], pa0, pa1, pa2, pa3, v0, v1);
                MMA16816(o[2 * jj + 1], pa0, pa1, pa2, pa3, v2, v3);
            }
        }
    }

    lA += __shfl_xor_sync(0xFFFFFFFFu, lA, 1);
    lA += __shfl_xor_sync(0xFFFFFFFFu, lA, 2);
    lB += __shfl_xor_sync(0xFFFFFFFFu, lB, 1);
    lB += __shfl_xor_sync(0xFFFFFFFFu, lB, 2);
    float invA = 1.0f / lA, invB = 1.0f / lB;
    __half* oA = O + (size_t)(b * SS + qA) * EMBED + h * 64;
    __half* oB = O + (size_t)(b * SS + qB) * EMBED + h * 64;
#pragma unroll
    for (int j = 0; j < 8; j++) {
        int c = j * 8 + 2 * t4;
        *(__half2*)(oA + c) = __floats2half2_rn(o[j][0] * invA, o[j][1] * invA);
        *(__half2*)(oB + c) = __floats2half2_rn(o[j][2] * invB, o[j][3] * invB);
    }
}

// ---------------- launch ------------------------------------------------------
extern "C" void kernel_launch(void* const* d_in, const int* in_sizes, int n_in,
                              void* d_out, int out_size) {
    const float* x   = (const float*)d_in[0];
    const float* rc  = (const float*)d_in[1];
    const float* rs  = (const float*)d_in[2];
    const float* Wq  = (const float*)d_in[3];
    const float* bq  = (const float*)d_in[4];
    const float* Wk  = (const float*)d_in[5];
    const float* bk  = (const float*)d_in[6];
    const float* Wv  = (const float*)d_in[7];
    const float* bv  = (const float*)d_in[8];
    const float* Wo  = (const float*)d_in[9];
    const float* bo  = (const float*)d_in[10];
    const float* W1  = (const float*)d_in[11];
    const float* b1  = (const float*)d_in[12];
    const float* W2  = (const float*)d_in[13];
    const float* b2  = (const float*)d_in[14];
    const float* g1  = (const float*)d_in[15];
    const float* be1 = (const float*)d_in[16];
    const float* g2  = (const float*)d_in[17];
    const float* be2 = (const float*)d_in[18];
    float* out = (float*)d_out;

    __half *nh, *qkvh, *attnh, *n2h, *hh;
    __half *wqkv, *wo, *w1, *w2;
    float *x1_, *bqkv;
    cudaGetSymbolAddress((void**)&nh, g_nh);
    cudaGetSymbolAddress((void**)&qkvh, g_qkvh);
    cudaGetSymbolAddress((void**)&attnh, g_attnh);
    cudaGetSymbolAddress((void**)&x1_, g_x1);
    cudaGetSymbolAddress((void**)&n2h, g_n2h);
    cudaGetSymbolAddress((void**)&hh, g_hh);
    cudaGetSymbolAddress((void**)&wqkv, g_wqkv);
    cudaGetSymbolAddress((void**)&wo, g_wo);
    cudaGetSymbolAddress((void**)&w1, g_w1);
    cudaGetSymbolAddress((void**)&w2, g_w2);
    cudaGetSymbolAddress((void**)&bqkv, g_bqkv);

    static bool attr_set = false;
    if (!attr_set) {
        cudaFuncSetAttribute(gemm_h<false, false, true, true>,
                             cudaFuncAttributeMaxDynamicSharedMemorySize, GEMM_SMEM);
        cudaFuncSetAttribute(gemm_h<false, true, false, false>,
                             cudaFuncAttributeMaxDynamicSharedMemorySize, GEMM_SMEM);
        cudaFuncSetAttribute(gemm_h<true, false, true, false>,
                             cudaFuncAttributeMaxDynamicSharedMemorySize, GEMM_SMEM);
        cudaFuncSetAttribute(attn_mma,
                             cudaFuncAttributeMaxDynamicSharedMemorySize, ATT_SMEM);
        attr_set = true;
    }

    convert_weights<<<3072, 256>>>(Wq, Wk, Wv, Wo, W1, W2, wqkv, wo, w1, w2,
                                   bq, bk, bv, bqkv);

    ln_kernel<<<ROWS, 256>>>(x, g1, be1, nh);

    dim3 gQKV(QKVS / 128, ROWS / 128);  // (24, 32)
    dim3 gE(EMBED / 128, ROWS / 128);   // (8, 32)
    dim3 gF(FFN / 128, ROWS / 128);     // (32, 32)

    gemm_h<false, false, true, true><<<gQKV, 256, GEMM_SMEM>>>(
        nh, wqkv, bqkv, nullptr, qkvh, ROWS, QKVS, EMBED, rc, rs);

    attn_mma<<<dim3(SS / 128, BB * HEADS), 256, ATT_SMEM>>>(qkvh, attnh);

    gemm_h<false, true, false, false><<<gE, 256, GEMM_SMEM>>>(
        attnh, wo, bo, x, x1_, ROWS, EMBED, EMBED, nullptr, nullptr);

    ln_kernel<<<ROWS, 256>>>(x1_, g2, be2, n2h);

    gemm_h<true, false, true, false><<<gF, 256, GEMM_SMEM>>>(
        n2h, w1, b1, nullptr, hh, ROWS, FFN, EMBED, nullptr, nullptr);
    gemm_h<false, true, false, false><<<gE, 256, GEMM_SMEM>>>(
        hh, w2, b2, x1_, out, ROWS, EMBED, FFN, nullptr, nullptr);
}